// round 16
// baseline (speedup 1.0000x reference)
#include <cuda_runtime.h>
#include <cuda_fp16.h>
#include <cstdint>
#include <cstddef>

#define D_MODEL  1024
#define N_HEADS  16
#define HEAD_DIM 64
#define BATCH    4
#define SEQ      2048
#define M_TOTAL  (BATCH * SEQ)   // 8192

// ---------------------------------------------------------------------------
// Scratch (no cudaMalloc allowed) — fp16 split buffers
// ---------------------------------------------------------------------------
__device__ __half g_xh[(size_t)M_TOTAL * D_MODEL];
__device__ __half g_qh[(size_t)M_TOTAL * D_MODEL];
__device__ __half g_kh[(size_t)M_TOTAL * D_MODEL];
__device__ __half g_vh[(size_t)M_TOTAL * D_MODEL];
__device__ __half g_ch[(size_t)M_TOTAL * D_MODEL];
__device__ __half g_wh[(size_t)4 * D_MODEL * D_MODEL];
__device__ __half g_wl[(size_t)D_MODEL * D_MODEL];    // lo kept only for W_o

// ---------------------------------------------------------------------------
// Baseline-PTX helpers (sm_80-class; compile under compute_103)
// ---------------------------------------------------------------------------
__device__ __forceinline__ uint32_t smem_to_u32(const void* p) {
    uint32_t a;
    asm("{ .reg .u64 t; cvta.to.shared.u64 t, %1; cvt.u32.u64 %0, t; }" : "=r"(a) : "l"(p));
    return a;
}
__device__ __forceinline__ void ldsm_x4(uint32_t* r, uint32_t addr) {
    asm volatile("ldmatrix.sync.aligned.m8n8.x4.shared.b16 {%0,%1,%2,%3}, [%4];"
        : "=r"(r[0]), "=r"(r[1]), "=r"(r[2]), "=r"(r[3]) : "r"(addr));
}
__device__ __forceinline__ void ldsm_x4_t(uint32_t* r, uint32_t addr) {
    asm volatile("ldmatrix.sync.aligned.m8n8.x4.trans.shared.b16 {%0,%1,%2,%3}, [%4];"
        : "=r"(r[0]), "=r"(r[1]), "=r"(r[2]), "=r"(r[3]) : "r"(addr));
}
// D += A(f16) * B(f16), m16n8k16, row.col, f32 accum
__device__ __forceinline__ void mma16816(float* d, const uint32_t* a, const uint32_t* b) {
    asm volatile(
        "mma.sync.aligned.m16n8k16.row.col.f32.f16.f16.f32 "
        "{%0,%1,%2,%3}, {%4,%5,%6,%7}, {%8,%9}, {%0,%1,%2,%3};"
        : "+f"(d[0]), "+f"(d[1]), "+f"(d[2]), "+f"(d[3])
        : "r"(a[0]), "r"(a[1]), "r"(a[2]), "r"(a[3]), "r"(b[0]), "r"(b[1]));
}
__device__ __forceinline__ void cp16(uint32_t smem, const void* g) {
    asm volatile("cp.async.cg.shared.global [%0], [%1], 16;" :: "r"(smem), "l"(g));
}
#define CP_COMMIT() asm volatile("cp.async.commit_group;" ::: "memory")
#define CP_WAIT(n)  asm volatile("cp.async.wait_group %0;" :: "n"(n) : "memory")

__device__ __forceinline__ float fast_exp2(float x) {
    float y;
    asm("ex2.approx.ftz.f32 %0, %1;" : "=f"(y) : "f"(x));
    return y;
}
__device__ __forceinline__ uint32_t pack_hf2(float a, float b) {
    __half2 h = __floats2half2_rn(a, b);
    return reinterpret_cast<uint32_t&>(h);
}
__device__ __forceinline__ uint32_t pack_hf2_hi(float a, float b, float& ra, float& rb) {
    __half2 h = __floats2half2_rn(a, b);
    float2 f = __half22float2(h);
    ra = a - f.x;
    rb = b - f.y;
    return reinterpret_cast<uint32_t&>(h);
}

// ---------------------------------------------------------------------------
// fp32 -> fp16 splits
// ---------------------------------------------------------------------------
// Wq/Wk/Wv: hi only into concat slots 0..2. W_o: hi into slot 3 + lo buffer.
__global__ __launch_bounds__(256)
void split_w_kernel(const float* __restrict__ W0, const float* __restrict__ W1,
                    const float* __restrict__ W2, const float* __restrict__ W3,
                    __half* __restrict__ hi, __half* __restrict__ lo, int n4)
{
    int i = blockIdx.x * 256 + threadIdx.x;
    if (i >= n4) return;
    int w = blockIdx.y;
    const float* src = (w == 0) ? W0 : (w == 1) ? W1 : (w == 2) ? W2 : W3;
    size_t o = (size_t)w * n4 + i;            // float4-unit offset into concat
    float4 v = ((const float4*)src)[i];
    float rx, ry, rz, rw;
    uint32_t h0 = pack_hf2_hi(v.x, v.y, rx, ry);
    uint32_t h1 = pack_hf2_hi(v.z, v.w, rz, rw);
    ((uint32_t*)hi)[2 * o]     = h0;
    ((uint32_t*)hi)[2 * o + 1] = h1;
    if (w == 3) {
        ((uint32_t*)lo)[2 * i]     = pack_hf2(rx, ry);
        ((uint32_t*)lo)[2 * i + 1] = pack_hf2(rz, rw);
    }
}

__global__ __launch_bounds__(256)
void split_hi_kernel(const float* __restrict__ x, __half* __restrict__ hi, int n4)
{
    int i = blockIdx.x * 256 + threadIdx.x;
    if (i >= n4) return;
    float4 v = ((const float4*)x)[i];
    ((uint32_t*)hi)[2 * i]     = pack_hf2(v.x, v.y);
    ((uint32_t*)hi)[2 * i + 1] = pack_hf2(v.z, v.w);
}

// ---------------------------------------------------------------------------
// Shared GEMM constants
// ---------------------------------------------------------------------------
#define BK 64
#define SROW 72                              // padded row, fp16 elements (144B)
#define TILE_B (128 * SROW * 2)              // 18432 bytes per tile
// 3-tile stage (Ah, Bh, Bl) for the O-projection 2-product GEMM
#define STAGE3_B (3 * TILE_B)                // 55296
#define SMEM_GEMM_O (2 * STAGE3_B)           // 110592
// 2-tile stage (Ah, Bh) for the pure-fp16 QKV GEMM
#define STAGE2_B (2 * TILE_B)                // 36864
#define SMEM_GEMM_QKV (2 * STAGE2_B)         // 73728

// ---------------------------------------------------------------------------
// Fused Q/K/V projection GEMM (pure fp16, 1 product): A = x (fp16-hi),
// B = concat(Wq,Wk,Wv) hi (3072x1024). Epilogue: fp16-hi out, routed by seg.
// ---------------------------------------------------------------------------
__global__ __launch_bounds__(256, 2)
void mma_gemm_qkv_kernel(const __half* __restrict__ Ah,
                         const __half* __restrict__ Bh,
                         __half* __restrict__ Qh,
                         __half* __restrict__ Kh, __half* __restrict__ Vh)
{
    extern __shared__ char smem[];
    const int tid  = threadIdx.x;
    const int warp = tid >> 5;
    const int lane = tid & 31;
    const int bm = blockIdx.y * 128;
    const int bn = blockIdx.x * 128;          // 0..2944 over concat N=3072
    const int wm = (warp >> 2) * 64;
    const int wn = (warp & 3) * 32;
    const int K = D_MODEL;

    const uint32_t sbase = smem_to_u32(smem);
    const int lr  = tid >> 3;
    const int lc8 = (tid & 7) << 3;

    auto issue = [&](int ch, int s) {
        const int k0g = ch * BK;
        const uint32_t st = sbase + s * STAGE2_B;
#pragma unroll
        for (int it = 0; it < 4; it++) {
            int r = lr + it * 32;
            uint32_t so = (uint32_t)(r * SROW + lc8) * 2;
            size_t ga = (size_t)(bm + r) * K + k0g + lc8;
            size_t gb = (size_t)(bn + r) * K + k0g + lc8;
            cp16(st + 0 * TILE_B + so, Ah + ga);
            cp16(st + 1 * TILE_B + so, Bh + gb);
        }
        CP_COMMIT();
    };

    const int a_row  = lane & 15;
    const int a_koff = (lane >> 4) << 3;
    const int b_row  = lane & 7;
    const int b_koff = ((lane >> 3) & 1) << 3;
    const int jsel8  = (lane >> 4) << 3;      // pair-select for x4 B loads

    float acc[4][4][4];
#pragma unroll
    for (int i = 0; i < 4; i++)
#pragma unroll
        for (int j = 0; j < 4; j++)
#pragma unroll
            for (int t = 0; t < 4; t++) acc[i][j][t] = 0.f;

    const int nchunks = K / BK;
    issue(0, 0);
    for (int ch = 0; ch < nchunks; ch++) {
        const int s = ch & 1;
        if (ch + 1 < nchunks) { issue(ch + 1, 1 - s); CP_WAIT(1); }
        else                  { CP_WAIT(0); }
        __syncthreads();

        const uint32_t uAh = sbase + s * STAGE2_B;
        const uint32_t uBh = uAh + TILE_B;
#pragma unroll
        for (int ks = 0; ks < 4; ks++) {
            const int k0 = ks * 16;
            uint32_t ah[4][4], bh[2][4];
#pragma unroll
            for (int i = 0; i < 4; i++) {
                uint32_t off = (uint32_t)((wm + i * 16 + a_row) * SROW + k0 + a_koff) * 2;
                ldsm_x4(ah[i], uAh + off);
            }
#pragma unroll
            for (int jp = 0; jp < 2; jp++) {   // pair (2jp, 2jp+1)
                uint32_t off = (uint32_t)((wn + jp * 16 + jsel8 + b_row) * SROW + k0 + b_koff) * 2;
                ldsm_x4(bh[jp], uBh + off);
            }
#pragma unroll
            for (int i = 0; i < 4; i++)
#pragma unroll
                for (int jp = 0; jp < 2; jp++)
#pragma unroll
                    for (int u = 0; u < 2; u++)
                        mma16816(acc[i][2 * jp + u], ah[i], bh[jp] + 2 * u);
        }
        __syncthreads();
    }

    // epilogue: fp16-hi output, routed by segment of the concatenated N
    const int seg = bn >> 10;                 // 0=Q, 1=K, 2=V
    const int cn  = bn & 1023;
    __half* Chi = (seg == 0) ? Qh : (seg == 1) ? Kh : Vh;

    const int gr = lane >> 2;
    const int gc = (lane & 3) << 1;
#pragma unroll
    for (int i = 0; i < 4; i++) {
#pragma unroll
        for (int j = 0; j < 4; j++) {
            size_t r0 = (size_t)(bm + wm + i * 16 + gr) * D_MODEL + cn + wn + j * 8 + gc;
            size_t r1 = r0 + (size_t)8 * D_MODEL;
            *(uint32_t*)(Chi + r0) = pack_hf2(acc[i][j][0], acc[i][j][1]);
            *(uint32_t*)(Chi + r1) = pack_hf2(acc[i][j][2], acc[i][j][3]);
        }
    }
}

// ---------------------------------------------------------------------------
// O-projection GEMM (fp16 2-product, fp32 output).
// ---------------------------------------------------------------------------
__global__ __launch_bounds__(256, 2)
void mma_gemm_kernel(const __half* __restrict__ Ah,
                     const __half* __restrict__ Bh, const __half* __restrict__ Bl,
                     float* __restrict__ C, int M, int N, int K)
{
    extern __shared__ char smem[];
    const int tid  = threadIdx.x;
    const int warp = tid >> 5;
    const int lane = tid & 31;
    const int bm = blockIdx.y * 128;
    const int bn = blockIdx.x * 128;
    const int wm = (warp >> 2) * 64;
    const int wn = (warp & 3) * 32;

    const uint32_t sbase = smem_to_u32(smem);
    const int lr  = tid >> 3;
    const int lc8 = (tid & 7) << 3;

    auto issue = [&](int ch, int s) {
        const int k0g = ch * BK;
        const uint32_t st = sbase + s * STAGE3_B;
#pragma unroll
        for (int it = 0; it < 4; it++) {
            int r = lr + it * 32;
            uint32_t so = (uint32_t)(r * SROW + lc8) * 2;
            size_t ga = (size_t)(bm + r) * K + k0g + lc8;
            size_t gb = (size_t)(bn + r) * K + k0g + lc8;
            cp16(st + 0 * TILE_B + so, Ah + ga);
            cp16(st + 1 * TILE_B + so, Bh + gb);
            cp16(st + 2 * TILE_B + so, Bl + gb);
        }
        CP_COMMIT();
    };

    const int a_row  = lane & 15;
    const int a_koff = (lane >> 4) << 3;
    const int b_row  = lane & 7;
    const int b_koff = ((lane >> 3) & 1) << 3;
    const int jsel8  = (lane >> 4) << 3;

    float acc[4][4][4];
#pragma unroll
    for (int i = 0; i < 4; i++)
#pragma unroll
        for (int j = 0; j < 4; j++)
#pragma unroll
            for (int t = 0; t < 4; t++) acc[i][j][t] = 0.f;

    const int nchunks = K / BK;
    issue(0, 0);
    for (int ch = 0; ch < nchunks; ch++) {
        const int s = ch & 1;
        if (ch + 1 < nchunks) { issue(ch + 1, 1 - s); CP_WAIT(1); }
        else                  { CP_WAIT(0); }
        __syncthreads();

        const uint32_t uAh = sbase + s * STAGE3_B;
        const uint32_t uBh = uAh + TILE_B;
        const uint32_t uBl = uAh + 2 * TILE_B;
#pragma unroll
        for (int ks = 0; ks < 4; ks++) {
            const int k0 = ks * 16;
            uint32_t ah[4][4], bh[2][4], bl[2][4];
#pragma unroll
            for (int i = 0; i < 4; i++) {
                uint32_t off = (uint32_t)((wm + i * 16 + a_row) * SROW + k0 + a_koff) * 2;
                ldsm_x4(ah[i], uAh + off);
            }
#pragma unroll
            for (int jp = 0; jp < 2; jp++) {
                uint32_t off = (uint32_t)((wn + jp * 16 + jsel8 + b_row) * SROW + k0 + b_koff) * 2;
                ldsm_x4(bh[jp], uBh + off);
                ldsm_x4(bl[jp], uBl + off);
            }
#pragma unroll
            for (int i = 0; i < 4; i++)
#pragma unroll
                for (int jp = 0; jp < 2; jp++)
#pragma unroll
                    for (int u = 0; u < 2; u++) {
                        mma16816(acc[i][2 * jp + u], ah[i], bh[jp] + 2 * u);
                        mma16816(acc[i][2 * jp + u], ah[i], bl[jp] + 2 * u);
                    }
        }
        __syncthreads();
    }

    const int gr = lane >> 2;
    const int gc = (lane & 3) << 1;
#pragma unroll
    for (int i = 0; i < 4; i++) {
#pragma unroll
        for (int j = 0; j < 4; j++) {
            size_t r0 = (size_t)(bm + wm + i * 16 + gr) * N + bn + wn + j * 8 + gc;
            size_t r1 = r0 + (size_t)8 * N;
            *(float2*)(C + r0) = make_float2(acc[i][j][0], acc[i][j][1]);
            *(float2*)(C + r1) = make_float2(acc[i][j][2], acc[i][j][3]);
        }
    }
}

// ---------------------------------------------------------------------------
// Tensor-core causal flash attention (pure fp16 via mma.sync),
// 2-stage cp.async K/V pipeline, 2 CTAs/SM, heavy-tiles-first, x4 loads.
// ---------------------------------------------------------------------------
#define FSROW 72
#define KVARR_B (64 * FSROW * 2)                 // 9216 bytes per array
#define KVSTAGE_B (2 * KVARR_B)                  // 18432 per stage (K, V)
#define FSMEM (128 * FSROW * 2 + 2 * KVSTAGE_B)  // 55296 bytes

__global__ __launch_bounds__(256, 2)
void flash_mma_kernel(const __half* __restrict__ Qh,
                      const __half* __restrict__ Kh,
                      const __half* __restrict__ Vh,
                      __half* __restrict__ Oh)
{
    extern __shared__ char fsm[];
    char* sQh = fsm;                                   // [128][FSROW] fp16
    const uint32_t uQh = smem_to_u32(sQh);
    const uint32_t uKV = uQh + 128 * FSROW * 2;        // 2 stages of {K, V}

    const int tid  = threadIdx.x;
    const int warp = tid >> 5;
    const int lane = tid & 31;
    const int qi = (int)(gridDim.x - 1) - (int)blockIdx.x;   // heavy-first (LPT)
    const int bh_ = blockIdx.y;                // b*16+h
    const int b = bh_ >> 4, h = bh_ & 15;
    const int q0 = qi << 7;
    const int wm = warp << 4;

    const size_t base = (size_t)b * SEQ * D_MODEL + (size_t)h * HEAD_DIM;
    const __half* kvsrc[2] = { Kh + base, Vh + base };

    auto issueKV = [&](int kt, int s) {
        const uint32_t st = uKV + s * KVSTAGE_B;
#pragma unroll
        for (int it = 0; it < 4; it++) {
            int lin = tid + it * 256;          // 0..1023
            int arr = lin >> 9;                // 0..1
            int idx = lin & 511;
            int r   = idx >> 3;
            int c8  = (idx & 7) << 3;
            cp16(st + arr * KVARR_B + (uint32_t)(r * FSROW + c8) * 2,
                 kvsrc[arr] + (size_t)((kt << 6) + r) * D_MODEL + c8);
        }
        CP_COMMIT();
    };

    // ---- load Q tile + prefetch KV tile 0 ----
#pragma unroll
    for (int it = 0; it < 4; it++) {
        int lin = tid + it * 256;
        int r   = lin >> 3;
        int c8  = (lin & 7) << 3;
        uint4 t = *(const uint4*)(Qh + base + (size_t)(q0 + r) * D_MODEL + c8);
        char* d = sQh + (r * FSROW + c8) * 2;
        *(uint2*)(d)     = make_uint2(t.x, t.y);
        *(uint2*)(d + 8) = make_uint2(t.z, t.w);
    }
    issueKV(0, 0);
    __syncthreads();

    uint32_t qh[4][4];
    {
        const int ar = lane & 15;
        const int ak = (lane >> 4) << 3;
#pragma unroll
        for (int ks = 0; ks < 4; ks++) {
            uint32_t off = (uint32_t)((wm + ar) * FSROW + ks * 16 + ak) * 2;
            ldsm_x4(qh[ks], uQh + off);
        }
    }

    const float NEG = -1e30f;
    const float CSC = 0.125f * 1.4426950408889634f;
    float m0 = NEG, m1 = NEG, l0 = 0.f, l1 = 0.f;
    float ov[8][4];
#pragma unroll
    for (int j = 0; j < 8; j++)
#pragma unroll
        for (int t = 0; t < 4; t++) ov[j][t] = 0.f;

    const int r0g = q0 + wm + (lane >> 2);
    const int r1g = r0g + 8;
    const int br  = lane & 7;
    const int bk  = ((lane >> 3) & 1) << 3;
    const int vr  = lane & 15;
    const int jsel8 = (lane >> 4) << 3;        // pair-select for x4 loads

    const int kend = 2 * qi + 2;
    for (int kt = 0; kt < kend; kt++) {
        const int s = kt & 1;
        if (kt + 1 < kend) { issueKV(kt + 1, 1 - s); CP_WAIT(1); }
        else               { CP_WAIT(0); }
        __syncthreads();

        const uint32_t uKs = uKV + s * KVSTAGE_B;
        const uint32_t uVs = uKs + KVARR_B;

        // ---- S = Q K^T (paired x4 K loads) ----
        float sreg[8][4];
#pragma unroll
        for (int j = 0; j < 8; j++)
#pragma unroll
            for (int t = 0; t < 4; t++) sreg[j][t] = 0.f;

#pragma unroll
        for (int jp = 0; jp < 4; jp++) {
#pragma unroll
            for (int ks = 0; ks < 4; ks++) {
                uint32_t kbh[4];
                uint32_t off = (uint32_t)((jp * 16 + jsel8 + br) * FSROW + ks * 16 + bk) * 2;
                ldsm_x4(kbh, uKs + off);
                mma16816(sreg[2 * jp],     qh[ks], kbh);
                mma16816(sreg[2 * jp + 1], qh[ks], kbh + 2);
            }
        }

        const bool diag = (kt >= 2 * qi);
#pragma unroll
        for (int j = 0; j < 8; j++) {
            sreg[j][0] *= CSC; sreg[j][1] *= CSC; sreg[j][2] *= CSC; sreg[j][3] *= CSC;
            if (diag) {
                int cb = (kt << 6) + j * 8 + ((lane & 3) << 1);
                if (cb     > r0g) sreg[j][0] = NEG;
                if (cb + 1 > r0g) sreg[j][1] = NEG;
                if (cb     > r1g) sreg[j][2] = NEG;
                if (cb + 1 > r1g) sreg[j][3] = NEG;
            }
        }

        float rm0 = NEG, rm1 = NEG;
#pragma unroll
        for (int j = 0; j < 8; j++) {
            rm0 = fmaxf(rm0, fmaxf(sreg[j][0], sreg[j][1]));
            rm1 = fmaxf(rm1, fmaxf(sreg[j][2], sreg[j][3]));
        }
        rm0 = fmaxf(rm0, __shfl_xor_sync(0xffffffffu, rm0, 1));
        rm0 = fmaxf(rm0, __shfl_xor_sync(0xffffffffu, rm0, 2));
        rm1 = fmaxf(rm1, __shfl_xor_sync(0xffffffffu, rm1, 1));
        rm1 = fmaxf(rm1, __shfl_xor_sync(0xffffffffu, rm1, 2));

        float mn0 = fmaxf(m0, rm0);
        float mn1 = fmaxf(m1, rm1);
        float sc0 = fast_exp2(m0 - mn0);
        float sc1 = fast_exp2(m1 - mn1);
        m0 = mn0; m1 = mn1;
#pragma unroll
        for (int j = 0; j < 8; j++) {
            ov[j][0] *= sc0; ov[j][1] *= sc0;
            ov[j][2] *= sc1; ov[j][3] *= sc1;
        }

        // ---- exp, pack P, P·V (paired x4 trans V loads) ----
        float rs0 = 0.f, rs1 = 0.f;
#pragma unroll
        for (int kk = 0; kk < 4; kk++) {
            uint32_t pah[4];
#pragma unroll
            for (int u = 0; u < 2; u++) {
                int t = 2 * kk + u;
                float p0 = fast_exp2(sreg[t][0] - mn0);
                float p1 = fast_exp2(sreg[t][1] - mn0);
                float p2 = fast_exp2(sreg[t][2] - mn1);
                float p3 = fast_exp2(sreg[t][3] - mn1);
                rs0 += p0 + p1;
                rs1 += p2 + p3;
                pah[2 * u]     = pack_hf2(p0, p1);
                pah[2 * u + 1] = pack_hf2(p2, p3);
            }
#pragma unroll
            for (int jvp = 0; jvp < 4; jvp++) {
                uint32_t vbh[4];
                uint32_t off = (uint32_t)((kk * 16 + vr) * FSROW + jvp * 16 + jsel8) * 2;
                ldsm_x4_t(vbh, uVs + off);
                mma16816(ov[2 * jvp],     pah, vbh);
                mma16816(ov[2 * jvp + 1], pah, vbh + 2);
            }
        }
        rs0 += __shfl_xor_sync(0xffffffffu, rs0, 1);
        rs0 += __shfl_xor_sync(0xffffffffu, rs0, 2);
        rs1 += __shfl_xor_sync(0xffffffffu, rs1, 1);
        rs1 += __shfl_xor_sync(0xffffffffu, rs1, 2);
        l0 = l0 * sc0 + rs0;
        l1 = l1 * sc1 + rs1;

        __syncthreads();
    }

    float rinv0 = 1.0f / l0;
    float rinv1 = 1.0f / l1;
    size_t orow0 = base + (size_t)(q0 + wm + (lane >> 2)) * D_MODEL;
    size_t orow1 = orow0 + (size_t)8 * D_MODEL;
    int colb = ((lane & 3) << 1);
#pragma unroll
    for (int jv = 0; jv < 8; jv++) {
        int c = jv * 8 + colb;
        *(uint32_t*)(Oh + orow0 + c) = pack_hf2(ov[jv][0] * rinv0, ov[jv][1] * rinv0);
        *(uint32_t*)(Oh + orow1 + c) = pack_hf2(ov[jv][2] * rinv1, ov[jv][3] * rinv1);
    }
}

// ---------------------------------------------------------------------------
// Launch
// ---------------------------------------------------------------------------
extern "C" void kernel_launch(void* const* d_in, const int* in_sizes, int n_in,
                              void* d_out, int out_size)
{
    const float* x   = (const float*)d_in[0];
    const float* W_q = (const float*)d_in[1];
    const float* W_k = (const float*)d_in[2];
    const float* W_v = (const float*)d_in[3];
    const float* W_o = (const float*)d_in[4];
    float* out = (float*)d_out;

    __half *pxh, *pqh, *pkh, *pvh, *pch, *pwh, *pwl;
    cudaGetSymbolAddress((void**)&pxh, g_xh);
    cudaGetSymbolAddress((void**)&pqh, g_qh);
    cudaGetSymbolAddress((void**)&pkh, g_kh);
    cudaGetSymbolAddress((void**)&pvh, g_vh);
    cudaGetSymbolAddress((void**)&pch, g_ch);
    cudaGetSymbolAddress((void**)&pwh, g_wh);
    cudaGetSymbolAddress((void**)&pwl, g_wl);

    cudaFuncSetAttribute(mma_gemm_qkv_kernel,
                         cudaFuncAttributeMaxDynamicSharedMemorySize, SMEM_GEMM_QKV);
    cudaFuncSetAttribute(mma_gemm_kernel,
                         cudaFuncAttributeMaxDynamicSharedMemorySize, SMEM_GEMM_O);
    cudaFuncSetAttribute(flash_mma_kernel,
                         cudaFuncAttributeMaxDynamicSharedMemorySize, FSMEM);

    const size_t WSZ = (size_t)D_MODEL * D_MODEL;   // 1048576
    const int nx4 = (int)((size_t)M_TOTAL * D_MODEL / 4);
    const int nw4 = (int)(WSZ / 4);

    // x: hi only; Wq/Wk/Wv: hi only; W_o: hi + lo
    split_hi_kernel<<<(nx4 + 255) / 256, 256>>>(x, pxh, nx4);
    dim3 gSplitW((nw4 + 255) / 256, 4);
    split_w_kernel<<<gSplitW, 256>>>(W_q, W_k, W_v, W_o, pwh, pwl, nw4);

    // fused Q/K/V projection (pure fp16): N = 3072 over concatenated weights
    dim3 gQKV(3 * D_MODEL / 128, M_TOTAL / 128);    // (24, 64)
    mma_gemm_qkv_kernel<<<gQKV, 256, SMEM_GEMM_QKV>>>(pxh, pwh, pqh, pkh, pvh);

    dim3 gFlash(SEQ / 128, BATCH * N_HEADS);        // (16, 64)
    flash_mma_kernel<<<gFlash, 256, FSMEM>>>(pqh, pkh, pvh, pch);

    // O projection (2-product): fp32 output
    dim3 gGemm(D_MODEL / 128, M_TOTAL / 128);       // (8, 64)
    mma_gemm_kernel<<<gGemm, 256, SMEM_GEMM_O>>>(pch, pwh + 3 * WSZ, pwl,
                                                 out, M_TOTAL, D_MODEL, D_MODEL);
}

// round 17
// speedup vs baseline: 1.5704x; 1.5704x over previous
#include <cuda_runtime.h>
#include <cuda_fp16.h>
#include <cstdint>
#include <cstddef>

#define D_MODEL  1024
#define N_HEADS  16
#define HEAD_DIM 64
#define BATCH    4
#define SEQ      2048
#define M_TOTAL  (BATCH * SEQ)   // 8192

// ---------------------------------------------------------------------------
// Scratch (no cudaMalloc allowed) — fp16 split buffers
// ---------------------------------------------------------------------------
__device__ __half g_xh[(size_t)M_TOTAL * D_MODEL];
__device__ __half g_qh[(size_t)M_TOTAL * D_MODEL];
__device__ __half g_kh[(size_t)M_TOTAL * D_MODEL];
__device__ __half g_vh[(size_t)M_TOTAL * D_MODEL];
__device__ __half g_ch[(size_t)M_TOTAL * D_MODEL];
__device__ __half g_wh[(size_t)4 * D_MODEL * D_MODEL];
__device__ __half g_wl[(size_t)D_MODEL * D_MODEL];    // lo kept only for W_o

// ---------------------------------------------------------------------------
// Baseline-PTX helpers (sm_80-class; compile under compute_103)
// ---------------------------------------------------------------------------
__device__ __forceinline__ uint32_t smem_to_u32(const void* p) {
    uint32_t a;
    asm("{ .reg .u64 t; cvta.to.shared.u64 t, %1; cvt.u32.u64 %0, t; }" : "=r"(a) : "l"(p));
    return a;
}
__device__ __forceinline__ void ldsm_x4(uint32_t* r, uint32_t addr) {
    asm volatile("ldmatrix.sync.aligned.m8n8.x4.shared.b16 {%0,%1,%2,%3}, [%4];"
        : "=r"(r[0]), "=r"(r[1]), "=r"(r[2]), "=r"(r[3]) : "r"(addr));
}
__device__ __forceinline__ void ldsm_x4_t(uint32_t* r, uint32_t addr) {
    asm volatile("ldmatrix.sync.aligned.m8n8.x4.trans.shared.b16 {%0,%1,%2,%3}, [%4];"
        : "=r"(r[0]), "=r"(r[1]), "=r"(r[2]), "=r"(r[3]) : "r"(addr));
}
// D += A(f16) * B(f16), m16n8k16, row.col, f32 accum
__device__ __forceinline__ void mma16816(float* d, const uint32_t* a, const uint32_t* b) {
    asm volatile(
        "mma.sync.aligned.m16n8k16.row.col.f32.f16.f16.f32 "
        "{%0,%1,%2,%3}, {%4,%5,%6,%7}, {%8,%9}, {%0,%1,%2,%3};"
        : "+f"(d[0]), "+f"(d[1]), "+f"(d[2]), "+f"(d[3])
        : "r"(a[0]), "r"(a[1]), "r"(a[2]), "r"(a[3]), "r"(b[0]), "r"(b[1]));
}
__device__ __forceinline__ void cp16(uint32_t smem, const void* g) {
    asm volatile("cp.async.cg.shared.global [%0], [%1], 16;" :: "r"(smem), "l"(g));
}
#define CP_COMMIT() asm volatile("cp.async.commit_group;" ::: "memory")
#define CP_WAIT(n)  asm volatile("cp.async.wait_group %0;" :: "n"(n) : "memory")

__device__ __forceinline__ float fast_exp2(float x) {
    float y;
    asm("ex2.approx.ftz.f32 %0, %1;" : "=f"(y) : "f"(x));
    return y;
}
__device__ __forceinline__ uint32_t pack_hf2(float a, float b) {
    __half2 h = __floats2half2_rn(a, b);
    return reinterpret_cast<uint32_t&>(h);
}
__device__ __forceinline__ uint32_t pack_hf2_hi(float a, float b, float& ra, float& rb) {
    __half2 h = __floats2half2_rn(a, b);
    float2 f = __half22float2(h);
    ra = a - f.x;
    rb = b - f.y;
    return reinterpret_cast<uint32_t&>(h);
}

#define CSC_SCALE (0.125f * 1.4426950408889634f)   // (1/sqrt(Dh)) * log2(e)

// ---------------------------------------------------------------------------
// fp32 -> fp16 splits
// ---------------------------------------------------------------------------
// Wq/Wk/Wv: hi only into concat slots 0..2. W_o: hi into slot 3 + lo buffer.
__global__ __launch_bounds__(256)
void split_w_kernel(const float* __restrict__ W0, const float* __restrict__ W1,
                    const float* __restrict__ W2, const float* __restrict__ W3,
                    __half* __restrict__ hi, __half* __restrict__ lo, int n4)
{
    int i = blockIdx.x * 256 + threadIdx.x;
    if (i >= n4) return;
    int w = blockIdx.y;
    const float* src = (w == 0) ? W0 : (w == 1) ? W1 : (w == 2) ? W2 : W3;
    size_t o = (size_t)w * n4 + i;            // float4-unit offset into concat
    float4 v = ((const float4*)src)[i];
    float rx, ry, rz, rw;
    uint32_t h0 = pack_hf2_hi(v.x, v.y, rx, ry);
    uint32_t h1 = pack_hf2_hi(v.z, v.w, rz, rw);
    ((uint32_t*)hi)[2 * o]     = h0;
    ((uint32_t*)hi)[2 * o + 1] = h1;
    if (w == 3) {
        ((uint32_t*)lo)[2 * i]     = pack_hf2(rx, ry);
        ((uint32_t*)lo)[2 * i + 1] = pack_hf2(rz, rw);
    }
}

__global__ __launch_bounds__(256)
void split_hi_kernel(const float* __restrict__ x, __half* __restrict__ hi, int n4)
{
    int i = blockIdx.x * 256 + threadIdx.x;
    if (i >= n4) return;
    float4 v = ((const float4*)x)[i];
    ((uint32_t*)hi)[2 * i]     = pack_hf2(v.x, v.y);
    ((uint32_t*)hi)[2 * i + 1] = pack_hf2(v.z, v.w);
}

// ---------------------------------------------------------------------------
// Shared GEMM constants
// ---------------------------------------------------------------------------
#define BK 64
#define SROW 72                              // padded row, fp16 elements (144B)
#define TILE_B (128 * SROW * 2)              // 18432 bytes per tile
// 3-tile stage (Ah, Bh, Bl) for the O-projection 2-product GEMM
#define STAGE3_B (3 * TILE_B)                // 55296
#define SMEM_GEMM_O (2 * STAGE3_B)           // 110592
// 2-tile stage (Ah, Bh) for the pure-fp16 QKV GEMM
#define STAGE2_B (2 * TILE_B)                // 36864
#define SMEM_GEMM_QKV (2 * STAGE2_B)         // 73728

// ---------------------------------------------------------------------------
// Fused Q/K/V projection GEMM (pure fp16, 1 product): A = x (fp16-hi),
// B = concat(Wq,Wk,Wv) hi (3072x1024). Epilogue: fp16-hi out, routed by seg.
// Q segment is pre-scaled by CSC_SCALE (softmax scale folded into Q).
// ---------------------------------------------------------------------------
__global__ __launch_bounds__(256, 2)
void mma_gemm_qkv_kernel(const __half* __restrict__ Ah,
                         const __half* __restrict__ Bh,
                         __half* __restrict__ Qh,
                         __half* __restrict__ Kh, __half* __restrict__ Vh)
{
    extern __shared__ char smem[];
    const int tid  = threadIdx.x;
    const int warp = tid >> 5;
    const int lane = tid & 31;
    const int bm = blockIdx.y * 128;
    const int bn = blockIdx.x * 128;          // 0..2944 over concat N=3072
    const int wm = (warp >> 2) * 64;
    const int wn = (warp & 3) * 32;
    const int K = D_MODEL;

    const uint32_t sbase = smem_to_u32(smem);
    const int lr  = tid >> 3;
    const int lc8 = (tid & 7) << 3;

    auto issue = [&](int ch, int s) {
        const int k0g = ch * BK;
        const uint32_t st = sbase + s * STAGE2_B;
#pragma unroll
        for (int it = 0; it < 4; it++) {
            int r = lr + it * 32;
            uint32_t so = (uint32_t)(r * SROW + lc8) * 2;
            size_t ga = (size_t)(bm + r) * K + k0g + lc8;
            size_t gb = (size_t)(bn + r) * K + k0g + lc8;
            cp16(st + 0 * TILE_B + so, Ah + ga);
            cp16(st + 1 * TILE_B + so, Bh + gb);
        }
        CP_COMMIT();
    };

    const int a_row  = lane & 15;
    const int a_koff = (lane >> 4) << 3;
    const int b_row  = lane & 7;
    const int b_koff = ((lane >> 3) & 1) << 3;
    const int jsel8  = (lane >> 4) << 3;      // pair-select for x4 B loads

    float acc[4][4][4];
#pragma unroll
    for (int i = 0; i < 4; i++)
#pragma unroll
        for (int j = 0; j < 4; j++)
#pragma unroll
            for (int t = 0; t < 4; t++) acc[i][j][t] = 0.f;

    const int nchunks = K / BK;
    issue(0, 0);
    for (int ch = 0; ch < nchunks; ch++) {
        const int s = ch & 1;
        if (ch + 1 < nchunks) { issue(ch + 1, 1 - s); CP_WAIT(1); }
        else                  { CP_WAIT(0); }
        __syncthreads();

        const uint32_t uAh = sbase + s * STAGE2_B;
        const uint32_t uBh = uAh + TILE_B;
#pragma unroll
        for (int ks = 0; ks < 4; ks++) {
            const int k0 = ks * 16;
            uint32_t ah[4][4], bh[2][4];
#pragma unroll
            for (int i = 0; i < 4; i++) {
                uint32_t off = (uint32_t)((wm + i * 16 + a_row) * SROW + k0 + a_koff) * 2;
                ldsm_x4(ah[i], uAh + off);
            }
#pragma unroll
            for (int jp = 0; jp < 2; jp++) {   // pair (2jp, 2jp+1)
                uint32_t off = (uint32_t)((wn + jp * 16 + jsel8 + b_row) * SROW + k0 + b_koff) * 2;
                ldsm_x4(bh[jp], uBh + off);
            }
#pragma unroll
            for (int i = 0; i < 4; i++)
#pragma unroll
                for (int jp = 0; jp < 2; jp++)
#pragma unroll
                    for (int u = 0; u < 2; u++)
                        mma16816(acc[i][2 * jp + u], ah[i], bh[jp] + 2 * u);
        }
        __syncthreads();
    }

    // epilogue: fp16-hi output, routed by segment; Q pre-scaled by CSC_SCALE
    const int seg = bn >> 10;                 // 0=Q, 1=K, 2=V
    const int cn  = bn & 1023;
    __half* Chi = (seg == 0) ? Qh : (seg == 1) ? Kh : Vh;
    const float osc = (seg == 0) ? CSC_SCALE : 1.0f;

    const int gr = lane >> 2;
    const int gc = (lane & 3) << 1;
#pragma unroll
    for (int i = 0; i < 4; i++) {
#pragma unroll
        for (int j = 0; j < 4; j++) {
            size_t r0 = (size_t)(bm + wm + i * 16 + gr) * D_MODEL + cn + wn + j * 8 + gc;
            size_t r1 = r0 + (size_t)8 * D_MODEL;
            *(uint32_t*)(Chi + r0) = pack_hf2(acc[i][j][0] * osc, acc[i][j][1] * osc);
            *(uint32_t*)(Chi + r1) = pack_hf2(acc[i][j][2] * osc, acc[i][j][3] * osc);
        }
    }
}

// ---------------------------------------------------------------------------
// O-projection GEMM (fp16 2-product, fp32 output).
// ---------------------------------------------------------------------------
__global__ __launch_bounds__(256, 2)
void mma_gemm_kernel(const __half* __restrict__ Ah,
                     const __half* __restrict__ Bh, const __half* __restrict__ Bl,
                     float* __restrict__ C, int M, int N, int K)
{
    extern __shared__ char smem[];
    const int tid  = threadIdx.x;
    const int warp = tid >> 5;
    const int lane = tid & 31;
    const int bm = blockIdx.y * 128;
    const int bn = blockIdx.x * 128;
    const int wm = (warp >> 2) * 64;
    const int wn = (warp & 3) * 32;

    const uint32_t sbase = smem_to_u32(smem);
    const int lr  = tid >> 3;
    const int lc8 = (tid & 7) << 3;

    auto issue = [&](int ch, int s) {
        const int k0g = ch * BK;
        const uint32_t st = sbase + s * STAGE3_B;
#pragma unroll
        for (int it = 0; it < 4; it++) {
            int r = lr + it * 32;
            uint32_t so = (uint32_t)(r * SROW + lc8) * 2;
            size_t ga = (size_t)(bm + r) * K + k0g + lc8;
            size_t gb = (size_t)(bn + r) * K + k0g + lc8;
            cp16(st + 0 * TILE_B + so, Ah + ga);
            cp16(st + 1 * TILE_B + so, Bh + gb);
            cp16(st + 2 * TILE_B + so, Bl + gb);
        }
        CP_COMMIT();
    };

    const int a_row  = lane & 15;
    const int a_koff = (lane >> 4) << 3;
    const int b_row  = lane & 7;
    const int b_koff = ((lane >> 3) & 1) << 3;
    const int jsel8  = (lane >> 4) << 3;

    float acc[4][4][4];
#pragma unroll
    for (int i = 0; i < 4; i++)
#pragma unroll
        for (int j = 0; j < 4; j++)
#pragma unroll
            for (int t = 0; t < 4; t++) acc[i][j][t] = 0.f;

    const int nchunks = K / BK;
    issue(0, 0);
    for (int ch = 0; ch < nchunks; ch++) {
        const int s = ch & 1;
        if (ch + 1 < nchunks) { issue(ch + 1, 1 - s); CP_WAIT(1); }
        else                  { CP_WAIT(0); }
        __syncthreads();

        const uint32_t uAh = sbase + s * STAGE3_B;
        const uint32_t uBh = uAh + TILE_B;
        const uint32_t uBl = uAh + 2 * TILE_B;
#pragma unroll
        for (int ks = 0; ks < 4; ks++) {
            const int k0 = ks * 16;
            uint32_t ah[4][4], bh[2][4], bl[2][4];
#pragma unroll
            for (int i = 0; i < 4; i++) {
                uint32_t off = (uint32_t)((wm + i * 16 + a_row) * SROW + k0 + a_koff) * 2;
                ldsm_x4(ah[i], uAh + off);
            }
#pragma unroll
            for (int jp = 0; jp < 2; jp++) {
                uint32_t off = (uint32_t)((wn + jp * 16 + jsel8 + b_row) * SROW + k0 + b_koff) * 2;
                ldsm_x4(bh[jp], uBh + off);
                ldsm_x4(bl[jp], uBl + off);
            }
#pragma unroll
            for (int i = 0; i < 4; i++)
#pragma unroll
                for (int jp = 0; jp < 2; jp++)
#pragma unroll
                    for (int u = 0; u < 2; u++) {
                        mma16816(acc[i][2 * jp + u], ah[i], bh[jp] + 2 * u);
                        mma16816(acc[i][2 * jp + u], ah[i], bl[jp] + 2 * u);
                    }
        }
        __syncthreads();
    }

    const int gr = lane >> 2;
    const int gc = (lane & 3) << 1;
#pragma unroll
    for (int i = 0; i < 4; i++) {
#pragma unroll
        for (int j = 0; j < 4; j++) {
            size_t r0 = (size_t)(bm + wm + i * 16 + gr) * N + bn + wn + j * 8 + gc;
            size_t r1 = r0 + (size_t)8 * N;
            *(float2*)(C + r0) = make_float2(acc[i][j][0], acc[i][j][1]);
            *(float2*)(C + r1) = make_float2(acc[i][j][2], acc[i][j][3]);
        }
    }
}

// ---------------------------------------------------------------------------
// Tensor-core causal flash attention (pure fp16 via mma.sync),
// 2-stage cp.async K/V pipeline, 2 CTAs/SM, heavy-tiles-first, x4 loads.
// Q is pre-scaled by CSC_SCALE, so S comes out directly in log2 units.
// ---------------------------------------------------------------------------
#define FSROW 72
#define KVARR_B (64 * FSROW * 2)                 // 9216 bytes per array
#define KVSTAGE_B (2 * KVARR_B)                  // 18432 per stage (K, V)
#define FSMEM (128 * FSROW * 2 + 2 * KVSTAGE_B)  // 55296 bytes

__global__ __launch_bounds__(256, 2)
void flash_mma_kernel(const __half* __restrict__ Qh,
                      const __half* __restrict__ Kh,
                      const __half* __restrict__ Vh,
                      __half* __restrict__ Oh)
{
    extern __shared__ char fsm[];
    char* sQh = fsm;                                   // [128][FSROW] fp16
    const uint32_t uQh = smem_to_u32(sQh);
    const uint32_t uKV = uQh + 128 * FSROW * 2;        // 2 stages of {K, V}

    const int tid  = threadIdx.x;
    const int warp = tid >> 5;
    const int lane = tid & 31;
    const int qi = (int)(gridDim.x - 1) - (int)blockIdx.x;   // heavy-first (LPT)
    const int bh_ = blockIdx.y;                // b*16+h
    const int b = bh_ >> 4, h = bh_ & 15;
    const int q0 = qi << 7;
    const int wm = warp << 4;

    const size_t base = (size_t)b * SEQ * D_MODEL + (size_t)h * HEAD_DIM;
    const __half* kvsrc[2] = { Kh + base, Vh + base };

    auto issueKV = [&](int kt, int s) {
        const uint32_t st = uKV + s * KVSTAGE_B;
#pragma unroll
        for (int it = 0; it < 4; it++) {
            int lin = tid + it * 256;          // 0..1023
            int arr = lin >> 9;                // 0..1
            int idx = lin & 511;
            int r   = idx >> 3;
            int c8  = (idx & 7) << 3;
            cp16(st + arr * KVARR_B + (uint32_t)(r * FSROW + c8) * 2,
                 kvsrc[arr] + (size_t)((kt << 6) + r) * D_MODEL + c8);
        }
        CP_COMMIT();
    };

    // ---- load Q tile + prefetch KV tile 0 ----
#pragma unroll
    for (int it = 0; it < 4; it++) {
        int lin = tid + it * 256;
        int r   = lin >> 3;
        int c8  = (lin & 7) << 3;
        uint4 t = *(const uint4*)(Qh + base + (size_t)(q0 + r) * D_MODEL + c8);
        char* d = sQh + (r * FSROW + c8) * 2;
        *(uint2*)(d)     = make_uint2(t.x, t.y);
        *(uint2*)(d + 8) = make_uint2(t.z, t.w);
    }
    issueKV(0, 0);
    __syncthreads();

    uint32_t qh[4][4];
    {
        const int ar = lane & 15;
        const int ak = (lane >> 4) << 3;
#pragma unroll
        for (int ks = 0; ks < 4; ks++) {
            uint32_t off = (uint32_t)((wm + ar) * FSROW + ks * 16 + ak) * 2;
            ldsm_x4(qh[ks], uQh + off);
        }
    }

    const float NEG = -1e30f;
    float m0 = NEG, m1 = NEG, l0 = 0.f, l1 = 0.f;
    float ov[8][4];
#pragma unroll
    for (int j = 0; j < 8; j++)
#pragma unroll
        for (int t = 0; t < 4; t++) ov[j][t] = 0.f;

    const int r0g = q0 + wm + (lane >> 2);
    const int r1g = r0g + 8;
    const int br  = lane & 7;
    const int bk  = ((lane >> 3) & 1) << 3;
    const int vr  = lane & 15;
    const int jsel8 = (lane >> 4) << 3;        // pair-select for x4 loads

    const int kend = 2 * qi + 2;
    for (int kt = 0; kt < kend; kt++) {
        const int s = kt & 1;
        if (kt + 1 < kend) { issueKV(kt + 1, 1 - s); CP_WAIT(1); }
        else               { CP_WAIT(0); }
        __syncthreads();

        const uint32_t uKs = uKV + s * KVSTAGE_B;
        const uint32_t uVs = uKs + KVARR_B;

        // ---- S = Q K^T, already in log2 units (scale folded into Q) ----
        float sreg[8][4];
#pragma unroll
        for (int j = 0; j < 8; j++)
#pragma unroll
            for (int t = 0; t < 4; t++) sreg[j][t] = 0.f;

#pragma unroll
        for (int jp = 0; jp < 4; jp++) {
#pragma unroll
            for (int ks = 0; ks < 4; ks++) {
                uint32_t kbh[4];
                uint32_t off = (uint32_t)((jp * 16 + jsel8 + br) * FSROW + ks * 16 + bk) * 2;
                ldsm_x4(kbh, uKs + off);
                mma16816(sreg[2 * jp],     qh[ks], kbh);
                mma16816(sreg[2 * jp + 1], qh[ks], kbh + 2);
            }
        }

        // ---- causal mask (diagonal tiles only) ----
        if (kt >= 2 * qi) {
#pragma unroll
            for (int j = 0; j < 8; j++) {
                int cb = (kt << 6) + j * 8 + ((lane & 3) << 1);
                if (cb     > r0g) sreg[j][0] = NEG;
                if (cb + 1 > r0g) sreg[j][1] = NEG;
                if (cb     > r1g) sreg[j][2] = NEG;
                if (cb + 1 > r1g) sreg[j][3] = NEG;
            }
        }

        float rm0 = NEG, rm1 = NEG;
#pragma unroll
        for (int j = 0; j < 8; j++) {
            rm0 = fmaxf(rm0, fmaxf(sreg[j][0], sreg[j][1]));
            rm1 = fmaxf(rm1, fmaxf(sreg[j][2], sreg[j][3]));
        }
        rm0 = fmaxf(rm0, __shfl_xor_sync(0xffffffffu, rm0, 1));
        rm0 = fmaxf(rm0, __shfl_xor_sync(0xffffffffu, rm0, 2));
        rm1 = fmaxf(rm1, __shfl_xor_sync(0xffffffffu, rm1, 1));
        rm1 = fmaxf(rm1, __shfl_xor_sync(0xffffffffu, rm1, 2));

        float mn0 = fmaxf(m0, rm0);
        float mn1 = fmaxf(m1, rm1);
        float sc0 = fast_exp2(m0 - mn0);
        float sc1 = fast_exp2(m1 - mn1);
        m0 = mn0; m1 = mn1;
#pragma unroll
        for (int j = 0; j < 8; j++) {
            ov[j][0] *= sc0; ov[j][1] *= sc0;
            ov[j][2] *= sc1; ov[j][3] *= sc1;
        }

        // ---- exp, pack P, P·V (paired x4 trans V loads) ----
        float rs0 = 0.f, rs1 = 0.f;
#pragma unroll
        for (int kk = 0; kk < 4; kk++) {
            uint32_t pah[4];
#pragma unroll
            for (int u = 0; u < 2; u++) {
                int t = 2 * kk + u;
                float p0 = fast_exp2(sreg[t][0] - mn0);
                float p1 = fast_exp2(sreg[t][1] - mn0);
                float p2 = fast_exp2(sreg[t][2] - mn1);
                float p3 = fast_exp2(sreg[t][3] - mn1);
                rs0 += p0 + p1;
                rs1 += p2 + p3;
                pah[2 * u]     = pack_hf2(p0, p1);
                pah[2 * u + 1] = pack_hf2(p2, p3);
            }
#pragma unroll
            for (int jvp = 0; jvp < 4; jvp++) {
                uint32_t vbh[4];
                uint32_t off = (uint32_t)((kk * 16 + vr) * FSROW + jvp * 16 + jsel8) * 2;
                ldsm_x4_t(vbh, uVs + off);
                mma16816(ov[2 * jvp],     pah, vbh);
                mma16816(ov[2 * jvp + 1], pah, vbh + 2);
            }
        }
        rs0 += __shfl_xor_sync(0xffffffffu, rs0, 1);
        rs0 += __shfl_xor_sync(0xffffffffu, rs0, 2);
        rs1 += __shfl_xor_sync(0xffffffffu, rs1, 1);
        rs1 += __shfl_xor_sync(0xffffffffu, rs1, 2);
        l0 = l0 * sc0 + rs0;
        l1 = l1 * sc1 + rs1;

        __syncthreads();
    }

    float rinv0 = 1.0f / l0;
    float rinv1 = 1.0f / l1;
    size_t orow0 = base + (size_t)(q0 + wm + (lane >> 2)) * D_MODEL;
    size_t orow1 = orow0 + (size_t)8 * D_MODEL;
    int colb = ((lane & 3) << 1);
#pragma unroll
    for (int jv = 0; jv < 8; jv++) {
        int c = jv * 8 + colb;
        *(uint32_t*)(Oh + orow0 + c) = pack_hf2(ov[jv][0] * rinv0, ov[jv][1] * rinv0);
        *(uint32_t*)(Oh + orow1 + c) = pack_hf2(ov[jv][2] * rinv1, ov[jv][3] * rinv1);
    }
}

// ---------------------------------------------------------------------------
// Launch
// ---------------------------------------------------------------------------
extern "C" void kernel_launch(void* const* d_in, const int* in_sizes, int n_in,
                              void* d_out, int out_size)
{
    const float* x   = (const float*)d_in[0];
    const float* W_q = (const float*)d_in[1];
    const float* W_k = (const float*)d_in[2];
    const float* W_v = (const float*)d_in[3];
    const float* W_o = (const float*)d_in[4];
    float* out = (float*)d_out;

    __half *pxh, *pqh, *pkh, *pvh, *pch, *pwh, *pwl;
    cudaGetSymbolAddress((void**)&pxh, g_xh);
    cudaGetSymbolAddress((void**)&pqh, g_qh);
    cudaGetSymbolAddress((void**)&pkh, g_kh);
    cudaGetSymbolAddress((void**)&pvh, g_vh);
    cudaGetSymbolAddress((void**)&pch, g_ch);
    cudaGetSymbolAddress((void**)&pwh, g_wh);
    cudaGetSymbolAddress((void**)&pwl, g_wl);

    cudaFuncSetAttribute(mma_gemm_qkv_kernel,
                         cudaFuncAttributeMaxDynamicSharedMemorySize, SMEM_GEMM_QKV);
    cudaFuncSetAttribute(mma_gemm_kernel,
                         cudaFuncAttributeMaxDynamicSharedMemorySize, SMEM_GEMM_O);
    cudaFuncSetAttribute(flash_mma_kernel,
                         cudaFuncAttributeMaxDynamicSharedMemorySize, FSMEM);

    const size_t WSZ = (size_t)D_MODEL * D_MODEL;   // 1048576
    const int nx4 = (int)((size_t)M_TOTAL * D_MODEL / 4);
    const int nw4 = (int)(WSZ / 4);

    // x: hi only; Wq/Wk/Wv: hi only; W_o: hi + lo
    split_hi_kernel<<<(nx4 + 255) / 256, 256>>>(x, pxh, nx4);
    dim3 gSplitW((nw4 + 255) / 256, 4);
    split_w_kernel<<<gSplitW, 256>>>(W_q, W_k, W_v, W_o, pwh, pwl, nw4);

    // fused Q/K/V projection (pure fp16): N = 3072 over concatenated weights
    dim3 gQKV(3 * D_MODEL / 128, M_TOTAL / 128);    // (24, 64)
    mma_gemm_qkv_kernel<<<gQKV, 256, SMEM_GEMM_QKV>>>(pxh, pwh, pqh, pkh, pvh);

    dim3 gFlash(SEQ / 128, BATCH * N_HEADS);        // (16, 64)
    flash_mma_kernel<<<gFlash, 256, FSMEM>>>(pqh, pkh, pvh, pch);

    // O projection (2-product): fp32 output
    dim3 gGemm(D_MODEL / 128, M_TOTAL / 128);       // (8, 64)
    mma_gemm_kernel<<<gGemm, 256, SMEM_GEMM_O>>>(pch, pwh + 3 * WSZ, pwl,
                                                 out, M_TOTAL, D_MODEL, D_MODEL);
}